// round 5
// baseline (speedup 1.0000x reference)
#include <cuda_runtime.h>
#include <cuda_bf16.h>
#include <cstdint>
#include <cstddef>

// ===================== problem constants =====================
static constexpr int C_    = 512;
static constexpr int HW_   = 784;            // 28*28
static constexpr int B_    = 64;
static constexpr int MTOT  = B_ * HW_;       // 50176 = 392 * 128
static constexpr int BM    = 128;
static constexpr int BN    = 64;
static constexpr int BKB   = 128;            // k-chunk bytes (int8 => 128 k)
static constexpr int NCHUNK = C_ / BKB;      // 4
static constexpr int MTILES = MTOT / BM;     // 392
static constexpr int MT    = 2;              // m-tiles per CTA
static constexpr int QTOT  = MT * NCHUNK;    // 8

static constexpr uint8_t I8_P1 = 0x01;
static constexpr uint8_t I8_M1 = 0xFF;

// smem layout
static constexpr uint32_t TILE_A_SZ  = 16384;                     // 128 x 128B
static constexpr uint32_t TILE_B_SZ  = 8192;                      // 64 x 128B
static constexpr uint32_t OFF_PARAMS = 0;                         // 4 x 64 floats = 1024
static constexpr uint32_t OFF_EPI    = 1024;                      // 128x33 floats = 16896
static constexpr uint32_t OFF_A      = 17920;                     // 3 stages
static constexpr uint32_t OFF_B      = OFF_A + 3 * TILE_A_SZ;     // 67072
static constexpr uint32_t SMEM_BYTES = OFF_B + NCHUNK * TILE_B_SZ; // 99840
static_assert(SMEM_BYTES <= 113 * 1024, "2 CTAs/SM");

// ===================== device scratch =====================
__device__ uint8_t g_A[(size_t)MTOT * C_];   // sign(x+rb) as s8
__device__ uint8_t g_W[(size_t)C_ * C_];     // sign(W)    as s8
__device__ float g_alpha[C_];
__device__ float g_cs[C_];

// ===================== helpers =====================
#define DEV_INLINE __device__ __forceinline__

DEV_INLINE uint32_t smem_u32(const void* p) {
    uint32_t a;
    asm("{ .reg .u64 t; cvta.to.shared.u64 t, %1; cvt.u32.u64 %0, t; }" : "=r"(a) : "l"(p));
    return a;
}
DEV_INLINE void cp_async16(uint32_t dst, const void* src) {
    asm volatile("cp.async.cg.shared.global [%0], [%1], 16;"
                 :: "r"(dst), "l"(__cvta_generic_to_global(src)) : "memory");
}
DEV_INLINE void cp_commit() { asm volatile("cp.async.commit_group;" ::: "memory"); }
template <int N>
DEV_INLINE void cp_wait() { asm volatile("cp.async.wait_group %0;" :: "n"(N) : "memory"); }

DEV_INLINE void ldmatrix_x4(uint32_t* r, uint32_t addr) {
    asm volatile("ldmatrix.sync.aligned.m8n8.x4.shared.b16 {%0,%1,%2,%3}, [%4];"
                 : "=r"(r[0]), "=r"(r[1]), "=r"(r[2]), "=r"(r[3]) : "r"(addr));
}
// s8 IMMA, s32 accum, k=32 (same fragment layout as e4m3 variant)
DEV_INLINE void mma_s8(int* c, const uint32_t* a, const uint32_t* b) {
    asm volatile(
        "mma.sync.aligned.m16n8k32.row.col.s32.s8.s8.s32 "
        "{%0,%1,%2,%3},{%4,%5,%6,%7},{%8,%9},{%0,%1,%2,%3};"
        : "+r"(c[0]), "+r"(c[1]), "+r"(c[2]), "+r"(c[3])
        : "r"(a[0]), "r"(a[1]), "r"(a[2]), "r"(a[3]), "r"(b[0]), "r"(b[1]));
}
DEV_INLINE uint32_t sw_off(int row, int g) {
    return (uint32_t)(row * 128 + (((g ^ (row & 7))) << 4));
}

// ===================== kernel 1: fused prep (W binarize + const fold) + signcast =====
__global__ void lb_prepsign_kernel(const float* __restrict__ x, const float* __restrict__ rb,
                                   const float* __restrict__ W, const float* __restrict__ gamma,
                                   const float* __restrict__ beta, const float* __restrict__ mean,
                                   const float* __restrict__ var, const float* __restrict__ shift) {
    const int blk = blockIdx.x;
    const int tid = threadIdx.x;
    if (blk < 64) {
        // ---- prep: warp per output channel ----
        int warp = tid >> 5, lane = tid & 31;
        int o = blk * 8 + warp;
        const float4* Wr = (const float4*)(W + (size_t)o * C_);
        float s = 0.f;
#pragma unroll
        for (int i = 0; i < 4; i++) {
            float4 f = Wr[i * 32 + lane];
            s += fabsf(f.x) + fabsf(f.y) + fabsf(f.z) + fabsf(f.w);
            uchar4 u;
            u.x = f.x >= 0.f ? I8_P1 : I8_M1;
            u.y = f.y >= 0.f ? I8_P1 : I8_M1;
            u.z = f.z >= 0.f ? I8_P1 : I8_M1;
            u.w = f.w >= 0.f ? I8_P1 : I8_M1;
            *(uchar4*)(g_W + (size_t)o * C_ + (i * 32 + lane) * 4) = u;
        }
#pragma unroll
        for (int k = 16; k > 0; k >>= 1) s += __shfl_xor_sync(0xFFFFFFFFu, s, k);
        if (lane == 0) {
            float scale = s * (1.f / 512.f);
            float rstd  = rsqrtf(var[o] + 1e-5f);
            g_alpha[o] = gamma[o] * rstd * scale;
            g_cs[o]    = beta[o] - gamma[o] * mean[o] * rstd - shift[o];
        }
        return;
    }
    // ---- signcast: tile = 128 channels x 32 hw ----
    __shared__ uint8_t tile[128][33];
    int s2 = blk - 64;
    int hwb = s2 % 25;
    int r2  = s2 / 25;
    int c0  = (r2 & 3) * 128;
    int b   = r2 >> 2;
    int h0  = hwb * 32;
    int tx = tid & 31, ty = tid >> 5;
#pragma unroll
    for (int j = 0; j < 16; j++) {
        int cl = ty + j * 8;
        int c  = c0 + cl;
        int hw = h0 + tx;
        float v = 1.f;
        if (hw < HW_) v = x[((size_t)b * C_ + c) * HW_ + hw] + rb[c];
        tile[cl][tx] = v >= 0.f ? I8_P1 : I8_M1;
    }
    __syncthreads();
#pragma unroll
    for (int j = 0; j < 4; j++) {
        int hwl = ty + j * 8;
        int hw  = h0 + hwl;
        if (hw < HW_) {
            size_t m = (size_t)b * HW_ + hw;
            uchar4 u;
            u.x = tile[4 * tx + 0][hwl];
            u.y = tile[4 * tx + 1][hwl];
            u.z = tile[4 * tx + 2][hwl];
            u.w = tile[4 * tx + 3][hwl];
            *(uchar4*)(g_A + m * C_ + c0 + 4 * tx) = u;
        }
    }
}

// ===================== kernel 2: s8 IMMA GEMM + fused epilogue =====================
DEV_INLINE void load_a_chunk(uint32_t sb, int q, int mt0, int tid) {
    const int mt = mt0 + (q >> 2), kc = q & 3;
    const uint8_t* src = g_A + (size_t)mt * BM * C_ + kc * BKB;
    uint32_t dst = sb + OFF_A + (q % 3) * TILE_A_SZ;
#pragma unroll
    for (int i = tid; i < 1024; i += 256) {
        int row = i >> 3, g = i & 7;
        cp_async16(dst + sw_off(row, g), src + (size_t)row * C_ + g * 16);
    }
}

__global__ __launch_bounds__(256, 2)
void lb_gemm_kernel(const float* __restrict__ x, float* __restrict__ out,
                    const float* __restrict__ pr_slope, const float* __restrict__ pr_bias) {
    extern __shared__ char smem[];
    const uint32_t sb = smem_u32(smem);
    const int tid = threadIdx.x, lane = tid & 31, w = tid >> 5;
    const int n0  = blockIdx.x * BN;
    const int mt0 = blockIdx.y * MT;

    float* sp = (float*)(smem + OFF_PARAMS);   // [alpha|cs|slope|prb] x 64
    if (tid < 64) {
        sp[tid]       = g_alpha[n0 + tid];
        sp[64 + tid]  = g_cs[n0 + tid];
        sp[128 + tid] = pr_slope[n0 + tid];
        sp[192 + tid] = pr_bias[n0 + tid];
    }

    // ---- B tile: 64 n-rows x 512 k (4 chunks) ----  [group 0]
    for (int i = tid; i < 2048; i += 256) {
        int kc = i >> 9, row = (i >> 3) & 63, g = i & 7;
        cp_async16(sb + OFF_B + kc * TILE_B_SZ + sw_off(row, g),
                   g_W + (size_t)(n0 + row) * C_ + kc * BKB + g * 16);
    }
    cp_commit();
    load_a_chunk(sb, 0, mt0, tid); cp_commit();
    load_a_chunk(sb, 1, mt0, tid); cp_commit();

    const int m_off = (w & 1) * 64, n_q = w >> 1;   // n_q 0..3, 16 n each
    const int n_off = n_q * 16;
    const int ra      = lane & 15;
    const int ka_half = lane >> 4;
    const int rb_     = (lane & 7) + ((lane >> 4) << 3);
    const int kb_half = (lane >> 3) & 1;

    int acc[4][2][4];
#pragma unroll
    for (int mf = 0; mf < 4; mf++)
#pragma unroll
        for (int nf = 0; nf < 2; nf++)
#pragma unroll
            for (int e = 0; e < 4; e++) acc[mf][nf][e] = 0;

#pragma unroll 1
    for (int q = 0; q < QTOT; q++) {
        cp_wait<1>();
        __syncthreads();
        if (q + 2 < QTOT) load_a_chunk(sb, q + 2, mt0, tid);
        cp_commit();     // empty group near tail keeps wait<1> exact

        const uint32_t Ab = sb + OFF_A + (q % 3) * TILE_A_SZ;
        const uint32_t Bb = sb + OFF_B + (q & 3) * TILE_B_SZ;
#pragma unroll
        for (int ks = 0; ks < 4; ks++) {
            uint32_t afr[4][4];
#pragma unroll
            for (int mf = 0; mf < 4; mf++) {
                int row = m_off + mf * 16 + ra;
                ldmatrix_x4(afr[mf], Ab + sw_off(row, ks * 2 + ka_half));
            }
            uint32_t bfr[4];
            {
                int row = n_off + rb_;
                ldmatrix_x4(bfr, Bb + sw_off(row, ks * 2 + kb_half));
            }
#pragma unroll
            for (int mf = 0; mf < 4; mf++)
#pragma unroll
                for (int nf = 0; nf < 2; nf++)
                    mma_s8(acc[mf][nf], afr[mf], &bfr[nf * 2]);
        }

        if ((q & 3) == 3) {
            __syncthreads();
            const int mbase = (mt0 + (q >> 2)) * BM;
            float* epi = (float*)(smem + OFF_EPI);   // [128][33]
#pragma unroll 1
            for (int nc = 0; nc < 2; nc++) {
                if ((n_q >> 1) == nc) {
                    const int cb = (n_q & 1) * 16;
#pragma unroll
                    for (int mf = 0; mf < 4; mf++)
#pragma unroll
                        for (int nf = 0; nf < 2; nf++) {
                            int r = m_off + mf * 16 + (lane >> 2);
                            int c = cb + nf * 8 + (lane & 3) * 2;
                            epi[r * 33 + c]           = (float)acc[mf][nf][0];
                            epi[r * 33 + c + 1]       = (float)acc[mf][nf][1];
                            epi[(r + 8) * 33 + c]     = (float)acc[mf][nf][2];
                            epi[(r + 8) * 33 + c + 1] = (float)acc[mf][nf][3];
                        }
                }
                __syncthreads();
                {
                    const int nl = tid >> 3, ms = tid & 7;
                    const int n = n0 + nc * 32 + nl;
                    const float al  = sp[nc * 32 + nl];
                    const float c0v = sp[64 + nc * 32 + nl];
                    const float sl  = sp[128 + nc * 32 + nl];
                    const float pb  = sp[192 + nc * 32 + nl];
                    const int m = mbase + ms * 16;          // 784 % 16 == 0
                    const int bb = m / HW_, hw = m % HW_;
                    const size_t base = ((size_t)bb * C_ + n) * HW_ + hw;
#pragma unroll
                    for (int j = 0; j < 4; j++) {
                        float4 xv = *(const float4*)(x + base + j * 4);
                        float d0 = epi[(ms * 16 + j * 4 + 0) * 33 + nl];
                        float d1 = epi[(ms * 16 + j * 4 + 1) * 33 + nl];
                        float d2 = epi[(ms * 16 + j * 4 + 2) * 33 + nl];
                        float d3 = epi[(ms * 16 + j * 4 + 3) * 33 + nl];
                        float t0 = al * d0 + c0v + xv.x;
                        float t1 = al * d1 + c0v + xv.y;
                        float t2 = al * d2 + c0v + xv.z;
                        float t3 = al * d3 + c0v + xv.w;
                        float4 o;
                        o.x = (t0 > 0.f ? t0 : sl * t0) + pb;
                        o.y = (t1 > 0.f ? t1 : sl * t1) + pb;
                        o.z = (t2 > 0.f ? t2 : sl * t2) + pb;
                        o.w = (t3 > 0.f ? t3 : sl * t3) + pb;
                        *(float4*)(out + base + j * 4) = o;
                    }
                }
                __syncthreads();
            }
            if (q + 1 < QTOT) {
#pragma unroll
                for (int mf = 0; mf < 4; mf++)
#pragma unroll
                    for (int nf = 0; nf < 2; nf++)
#pragma unroll
                        for (int e = 0; e < 4; e++) acc[mf][nf][e] = 0;
            }
        }
    }
}

// ===================== launch =====================
extern "C" void kernel_launch(void* const* d_in, const int* in_sizes, int n_in,
                              void* d_out, int out_size) {
    const float* x     = (const float*)d_in[0];
    const float* rb    = (const float*)d_in[1];
    const float* W     = (const float*)d_in[2];
    const float* gamma = (const float*)d_in[3];
    const float* beta  = (const float*)d_in[4];
    const float* mean  = (const float*)d_in[5];
    const float* var   = (const float*)d_in[6];
    const float* slope = (const float*)d_in[7];
    const float* shift = (const float*)d_in[8];
    const float* prb   = (const float*)d_in[9];
    float* out = (float*)d_out;

    lb_prepsign_kernel<<<64 + 25 * 4 * B_, 256>>>(x, rb, W, gamma, beta, mean, var, shift);

    cudaFuncSetAttribute(lb_gemm_kernel, cudaFuncAttributeMaxDynamicSharedMemorySize, SMEM_BYTES);
    lb_gemm_kernel<<<dim3(C_ / BN, MTILES / MT), 256, SMEM_BYTES>>>(x, out, slope, prb);
}

// round 6
// speedup vs baseline: 1.2000x; 1.2000x over previous
#include <cuda_runtime.h>
#include <cuda_bf16.h>
#include <cstdint>
#include <cstddef>

// ===================== problem constants =====================
static constexpr int C_    = 512;
static constexpr int HW_   = 784;            // 28*28
static constexpr int B_    = 64;
static constexpr int MTOT  = B_ * HW_;       // 50176 = 392 * 128
static constexpr int BM    = 128;
static constexpr int BN    = 128;
static constexpr int BKB   = 128;            // k-chunk bytes (fp8 => 128 k)
static constexpr int NCHUNK = C_ / BKB;      // 4
static constexpr int MTILES = MTOT / BM;     // 392
static constexpr int MT    = 2;              // m-tiles per CTA

static constexpr uint8_t FP8_P1 = 0x38;
static constexpr uint8_t FP8_M1 = 0xB8;

// smem layout (dynamic)
static constexpr uint32_t OFF_PARAMS = 0;                        // 512 floats = 2048
static constexpr uint32_t OFF_RB     = 2048;                     // 512 floats = 2048
static constexpr uint32_t OFF_EPI    = 4096;                     // 128*33*4 = 16896
static constexpr uint32_t OFF_A      = 21504;                    // 1 stage, 16384
static constexpr uint32_t OFF_B      = 37888;                    // 4 chunks x 16384
static constexpr uint32_t SMEM_BYTES = OFF_B + NCHUNK * 16384;   // 103424
static_assert(OFF_EPI + 128 * 33 * 4 <= OFF_A, "epi fits");
static_assert(SMEM_BYTES <= 113 * 1024, "2 CTAs/SM");

// ===================== device scratch =====================
__device__ uint8_t g_W[(size_t)C_ * C_];     // sign(W) as e4m3 [o][c]
__device__ float g_alpha[C_];
__device__ float g_cs[C_];

// ===================== helpers =====================
#define DEV_INLINE __device__ __forceinline__

DEV_INLINE uint32_t smem_u32(const void* p) {
    uint32_t a;
    asm("{ .reg .u64 t; cvta.to.shared.u64 t, %1; cvt.u32.u64 %0, t; }" : "=r"(a) : "l"(p));
    return a;
}
DEV_INLINE void cp_async16(uint32_t dst, const void* src) {
    asm volatile("cp.async.cg.shared.global [%0], [%1], 16;"
                 :: "r"(dst), "l"(__cvta_generic_to_global(src)) : "memory");
}
DEV_INLINE void cp_commit() { asm volatile("cp.async.commit_group;" ::: "memory"); }
template <int N>
DEV_INLINE void cp_wait() { asm volatile("cp.async.wait_group %0;" :: "n"(N) : "memory"); }

DEV_INLINE void ldmatrix_x4(uint32_t* r, uint32_t addr) {
    asm volatile("ldmatrix.sync.aligned.m8n8.x4.shared.b16 {%0,%1,%2,%3}, [%4];"
                 : "=r"(r[0]), "=r"(r[1]), "=r"(r[2]), "=r"(r[3]) : "r"(addr));
}
DEV_INLINE void mma_fp8(float* c, const uint32_t* a, const uint32_t* b) {
    asm volatile(
        "mma.sync.aligned.m16n8k32.row.col.f32.e4m3.e4m3.f32 "
        "{%0,%1,%2,%3},{%4,%5,%6,%7},{%8,%9},{%0,%1,%2,%3};"
        : "+f"(c[0]), "+f"(c[1]), "+f"(c[2]), "+f"(c[3])
        : "r"(a[0]), "r"(a[1]), "r"(a[2]), "r"(a[3]), "r"(b[0]), "r"(b[1]));
}
DEV_INLINE uint32_t sw_off(int row, int g) {
    return (uint32_t)(row * 128 + (((g ^ (row & 7))) << 4));
}

// ===================== kernel 1: fold constants + binarize W =====================
__global__ void lb_prep_kernel(const float* __restrict__ W, const float* __restrict__ gamma,
                               const float* __restrict__ beta, const float* __restrict__ mean,
                               const float* __restrict__ var, const float* __restrict__ shift) {
    int warp = threadIdx.x >> 5, lane = threadIdx.x & 31;
    int o = blockIdx.x * 8 + warp;
    const float4* Wr = (const float4*)(W + (size_t)o * C_);
    float s = 0.f;
#pragma unroll
    for (int i = 0; i < 4; i++) {
        float4 f = Wr[i * 32 + lane];
        s += fabsf(f.x) + fabsf(f.y) + fabsf(f.z) + fabsf(f.w);
        uchar4 u;
        u.x = f.x >= 0.f ? FP8_P1 : FP8_M1;
        u.y = f.y >= 0.f ? FP8_P1 : FP8_M1;
        u.z = f.z >= 0.f ? FP8_P1 : FP8_M1;
        u.w = f.w >= 0.f ? FP8_P1 : FP8_M1;
        *(uchar4*)(g_W + (size_t)o * C_ + (i * 32 + lane) * 4) = u;
    }
#pragma unroll
    for (int k = 16; k > 0; k >>= 1) s += __shfl_xor_sync(0xFFFFFFFFu, s, k);
    if (lane == 0) {
        float scale = s * (1.f / 512.f);
        float rstd  = rsqrtf(var[o] + 1e-5f);
        g_alpha[o] = gamma[o] * rstd * scale;
        g_cs[o]    = beta[o] - gamma[o] * mean[o] * rstd - shift[o];
    }
}

// ===================== kernel 2: fused sign-convert + fp8 GEMM + epilogue =============
__global__ __launch_bounds__(256, 2)
void lb_gemm_kernel(const float* __restrict__ x, float* __restrict__ out,
                    const float* __restrict__ rb,
                    const float* __restrict__ pr_slope, const float* __restrict__ pr_bias) {
    extern __shared__ char smem[];
    const uint32_t sb = smem_u32(smem);
    const int tid = threadIdx.x, lane = tid & 31, w = tid >> 5;
    const int n0  = blockIdx.x * BN;
    const int mt0 = blockIdx.y * MT;

    float* sp   = (float*)(smem + OFF_PARAMS);   // [alpha|cs|slope|prb] x 128
    float* s_rb = (float*)(smem + OFF_RB);       // 512
    if (tid < 128) {
        sp[tid]       = g_alpha[n0 + tid];
        sp[128 + tid] = g_cs[n0 + tid];
        sp[256 + tid] = pr_slope[n0 + tid];
        sp[384 + tid] = pr_bias[n0 + tid];
    }
    for (int i = tid; i < C_; i += 256) s_rb[i] = rb[i];

    // ---- B tile via cp.async: 128 n-rows x 512 k (4 chunks resident) ----
    for (int i = tid; i < 4096; i += 256) {
        int kc = i >> 10, row = (i >> 3) & 127, g = i & 7;
        cp_async16(sb + OFF_B + kc * 16384 + sw_off(row, g),
                   g_W + (size_t)(n0 + row) * C_ + kc * BKB + g * 16);
    }
    cp_commit();

    const int m_off = (w & 1) * 64, n_off = (w >> 1) * 32;
    const int ra      = lane & 15;
    const int ka_half = lane >> 4;
    const int rb_     = (lane & 7) + ((lane >> 4) << 3);
    const int kb_half = (lane >> 3) & 1;

    // conversion assignment: warps (w&3) cover m rows, (w>>2) selects c half
    const int cv_mloc = (w & 3) * 32 + lane;     // 0..127
    const int cv_cgb  = (w >> 2) * 16;           // c-group base (4 c each)

#pragma unroll 1
    for (int it = 0; it < MT; it++) {
        const int mt = mt0 + it;
        // per-tile thread row -> (b, hw); groups of 4 m never cross batch (784%4==0),
        // but this thread's single m row is computed exactly:
        const int m_cv = mt * BM + cv_mloc;
        const int b_cv = m_cv / HW_, hw_cv = m_cv % HW_;
        const float* xb = x + ((size_t)b_cv * C_) * HW_ + hw_cv;

        float acc[4][4][4];
#pragma unroll
        for (int mf = 0; mf < 4; mf++)
#pragma unroll
            for (int nf = 0; nf < 4; nf++)
#pragma unroll
                for (int e = 0; e < 4; e++) acc[mf][nf][e] = 0.f;

#pragma unroll 1
        for (int kc = 0; kc < NCHUNK; kc++) {
            __syncthreads();   // A smem free (prev chunk fully consumed)

            // ---- fused conversion: x -> sign -> e4m3 bytes -> swizzled A smem ----
            {
                const int row = cv_mloc;
                const uint32_t rowbase = sb + OFF_A + row * 128;
                const int r7 = row & 7;
#pragma unroll 4
                for (int j = 0; j < 16; j++) {
                    const int cg = cv_cgb + j;          // 0..31
                    const int c  = kc * 128 + cg * 4;
                    float v0 = xb[(size_t)(c + 0) * HW_] + s_rb[c + 0];
                    float v1 = xb[(size_t)(c + 1) * HW_] + s_rb[c + 1];
                    float v2 = xb[(size_t)(c + 2) * HW_] + s_rb[c + 2];
                    float v3 = xb[(size_t)(c + 3) * HW_] + s_rb[c + 3];
                    uint32_t p = 0x38383838u
                        | ((__float_as_uint(v0) >> 31) << 7)
                        | ((__float_as_uint(v1) >> 31) << 15)
                        | ((__float_as_uint(v2) >> 31) << 23)
                        | ((__float_as_uint(v3) & 0x80000000u));
                    const int g = cg >> 2;
                    uint32_t addr = rowbase + (((uint32_t)(g ^ r7)) << 4) + (cg & 3) * 4;
                    asm volatile("st.shared.u32 [%0], %1;" :: "r"(addr), "r"(p) : "memory");
                }
            }
            if (it == 0 && kc == 0) cp_wait<0>();   // B resident before first MMA
            __syncthreads();

            // ---- MMA phase (identical to proven R4 path) ----
            const uint32_t Ab = sb + OFF_A;
            const uint32_t Bb = sb + OFF_B + kc * 16384;
#pragma unroll
            for (int ks = 0; ks < 4; ks++) {
                uint32_t afr[4][4];
#pragma unroll
                for (int mf = 0; mf < 4; mf++) {
                    int row = m_off + mf * 16 + ra;
                    ldmatrix_x4(afr[mf], Ab + sw_off(row, ks * 2 + ka_half));
                }
                uint32_t bfr[2][4];
#pragma unroll
                for (int p = 0; p < 2; p++) {
                    int row = n_off + p * 16 + rb_;
                    ldmatrix_x4(bfr[p], Bb + sw_off(row, ks * 2 + kb_half));
                }
#pragma unroll
                for (int mf = 0; mf < 4; mf++)
#pragma unroll
                    for (int nf = 0; nf < 4; nf++)
                        mma_fp8(acc[mf][nf], afr[mf], &bfr[nf >> 1][(nf & 1) * 2]);
            }
        }

        // ---- epilogue ----
        __syncthreads();
        const int mbase = mt * BM;
        float* epi = (float*)(smem + OFF_EPI);   // [128][33]
#pragma unroll 1
        for (int nc = 0; nc < 4; nc++) {
            if ((w >> 1) == nc) {
#pragma unroll
                for (int mf = 0; mf < 4; mf++)
#pragma unroll
                    for (int nf = 0; nf < 4; nf++) {
                        int r = m_off + mf * 16 + (lane >> 2);
                        int c = nf * 8 + (lane & 3) * 2;
                        epi[r * 33 + c]           = acc[mf][nf][0];
                        epi[r * 33 + c + 1]       = acc[mf][nf][1];
                        epi[(r + 8) * 33 + c]     = acc[mf][nf][2];
                        epi[(r + 8) * 33 + c + 1] = acc[mf][nf][3];
                    }
            }
            __syncthreads();
            {
                const int nl = tid >> 3, ms = tid & 7;
                const int n = n0 + nc * 32 + nl;
                const float al  = sp[nc * 32 + nl];
                const float c0v = sp[128 + nc * 32 + nl];
                const float sl  = sp[256 + nc * 32 + nl];
                const float pb  = sp[384 + nc * 32 + nl];
                const int m = mbase + ms * 16;          // 784 % 16 == 0
                const int bb = m / HW_, hw = m % HW_;
                const size_t base = ((size_t)bb * C_ + n) * HW_ + hw;
#pragma unroll
                for (int j = 0; j < 4; j++) {
                    float4 xv = *(const float4*)(x + base + j * 4);
                    float d0 = epi[(ms * 16 + j * 4 + 0) * 33 + nl];
                    float d1 = epi[(ms * 16 + j * 4 + 1) * 33 + nl];
                    float d2 = epi[(ms * 16 + j * 4 + 2) * 33 + nl];
                    float d3 = epi[(ms * 16 + j * 4 + 3) * 33 + nl];
                    float t0 = al * d0 + c0v + xv.x;
                    float t1 = al * d1 + c0v + xv.y;
                    float t2 = al * d2 + c0v + xv.z;
                    float t3 = al * d3 + c0v + xv.w;
                    float4 o;
                    o.x = (t0 > 0.f ? t0 : sl * t0) + pb;
                    o.y = (t1 > 0.f ? t1 : sl * t1) + pb;
                    o.z = (t2 > 0.f ? t2 : sl * t2) + pb;
                    o.w = (t3 > 0.f ? t3 : sl * t3) + pb;
                    *(float4*)(out + base + j * 4) = o;
                }
            }
            __syncthreads();
        }
    }
}

// ===================== launch =====================
extern "C" void kernel_launch(void* const* d_in, const int* in_sizes, int n_in,
                              void* d_out, int out_size) {
    const float* x     = (const float*)d_in[0];
    const float* rb    = (const float*)d_in[1];
    const float* W     = (const float*)d_in[2];
    const float* gamma = (const float*)d_in[3];
    const float* beta  = (const float*)d_in[4];
    const float* mean  = (const float*)d_in[5];
    const float* var   = (const float*)d_in[6];
    const float* slope = (const float*)d_in[7];
    const float* shift = (const float*)d_in[8];
    const float* prb   = (const float*)d_in[9];
    float* out = (float*)d_out;

    lb_prep_kernel<<<C_ / 8, 256>>>(W, gamma, beta, mean, var, shift);

    cudaFuncSetAttribute(lb_gemm_kernel, cudaFuncAttributeMaxDynamicSharedMemorySize, SMEM_BYTES);
    lb_gemm_kernel<<<dim3(C_ / BN, MTILES / MT), 256, SMEM_BYTES>>>(x, out, rb, slope, prb);
}

// round 7
// speedup vs baseline: 1.4297x; 1.1914x over previous
#include <cuda_runtime.h>
#include <cuda_bf16.h>
#include <cstdint>
#include <cstddef>

// ===================== problem constants =====================
static constexpr int C_    = 512;
static constexpr int HW_   = 784;            // 28*28
static constexpr int B_    = 64;
static constexpr int MTOT  = B_ * HW_;       // 50176 = 392 * 128
static constexpr int BM    = 128;
static constexpr int BN    = 128;
static constexpr int BKB   = 128;            // k-chunk bytes (fp8 => 128 k)
static constexpr int NCHUNK = C_ / BKB;      // 4
static constexpr int MTILES = MTOT / BM;     // 392
static constexpr int MT    = 2;              // m-tiles per CTA
static constexpr int QTOT  = MT * NCHUNK;    // 8

static constexpr uint8_t FP8_P1 = 0x38;
static constexpr uint8_t FP8_M1 = 0xB8;

// smem layout: epi | A(2 stages) | B(4 chunks resident)   -> 115,712 B (occ 2)
static constexpr uint32_t OFF_EPI    = 0;                        // 128*33*4 = 16896
static constexpr uint32_t OFF_A      = 17408;                    // 2 x 16384
static constexpr uint32_t OFF_B      = OFF_A + 2 * 16384;        // 50176
static constexpr uint32_t SMEM_BYTES = OFF_B + NCHUNK * 16384;   // 115712
static_assert(SMEM_BYTES <= 116224, "2 CTAs/SM");

// ===================== device scratch =====================
__device__ uint8_t g_A[(size_t)MTOT * C_];   // sign(x+rb) as e4m3 [m][c]
__device__ uint8_t g_W[(size_t)C_ * C_];     // sign(W)    as e4m3 [o][c]
__device__ float g_alpha[C_];
__device__ float g_cs[C_];

// ===================== helpers =====================
#define DEV_INLINE __device__ __forceinline__

DEV_INLINE uint32_t smem_u32(const void* p) {
    uint32_t a;
    asm("{ .reg .u64 t; cvta.to.shared.u64 t, %1; cvt.u32.u64 %0, t; }" : "=r"(a) : "l"(p));
    return a;
}
DEV_INLINE void cp_async16(uint32_t dst, const void* src) {
    asm volatile("cp.async.cg.shared.global [%0], [%1], 16;"
                 :: "r"(dst), "l"(__cvta_generic_to_global(src)) : "memory");
}
DEV_INLINE void cp_commit() { asm volatile("cp.async.commit_group;" ::: "memory"); }
template <int N>
DEV_INLINE void cp_wait() { asm volatile("cp.async.wait_group %0;" :: "n"(N) : "memory"); }

DEV_INLINE void ldmatrix_x4(uint32_t* r, uint32_t addr) {
    asm volatile("ldmatrix.sync.aligned.m8n8.x4.shared.b16 {%0,%1,%2,%3}, [%4];"
                 : "=r"(r[0]), "=r"(r[1]), "=r"(r[2]), "=r"(r[3]) : "r"(addr));
}
DEV_INLINE void mma_fp8(float* c, const uint32_t* a, const uint32_t* b) {
    asm volatile(
        "mma.sync.aligned.m16n8k32.row.col.f32.e4m3.e4m3.f32 "
        "{%0,%1,%2,%3},{%4,%5,%6,%7},{%8,%9},{%0,%1,%2,%3};"
        : "+f"(c[0]), "+f"(c[1]), "+f"(c[2]), "+f"(c[3])
        : "r"(a[0]), "r"(a[1]), "r"(a[2]), "r"(a[3]), "r"(b[0]), "r"(b[1]));
}
DEV_INLINE uint32_t sw_off(int row, int g) {
    return (uint32_t)(row * 128 + (((g ^ (row & 7))) << 4));
}

// ===================== kernel 1: fused W-prep + signcast =====================
__global__ void lb_prepsign_kernel(const float* __restrict__ x, const float* __restrict__ rb,
                                   const float* __restrict__ W, const float* __restrict__ gamma,
                                   const float* __restrict__ beta, const float* __restrict__ mean,
                                   const float* __restrict__ var, const float* __restrict__ shift) {
    const int blk = blockIdx.x;
    const int tid = threadIdx.x;
    if (blk < 64) {
        // ---- prep: warp per output channel ----
        int warp = tid >> 5, lane = tid & 31;
        int o = blk * 8 + warp;
        const float4* Wr = (const float4*)(W + (size_t)o * C_);
        float s = 0.f;
#pragma unroll
        for (int i = 0; i < 4; i++) {
            float4 f = Wr[i * 32 + lane];
            s += fabsf(f.x) + fabsf(f.y) + fabsf(f.z) + fabsf(f.w);
            uchar4 u;
            u.x = f.x >= 0.f ? FP8_P1 : FP8_M1;
            u.y = f.y >= 0.f ? FP8_P1 : FP8_M1;
            u.z = f.z >= 0.f ? FP8_P1 : FP8_M1;
            u.w = f.w >= 0.f ? FP8_P1 : FP8_M1;
            *(uchar4*)(g_W + (size_t)o * C_ + (i * 32 + lane) * 4) = u;
        }
#pragma unroll
        for (int k = 16; k > 0; k >>= 1) s += __shfl_xor_sync(0xFFFFFFFFu, s, k);
        if (lane == 0) {
            float scale = s * (1.f / 512.f);
            float rstd  = rsqrtf(var[o] + 1e-5f);
            g_alpha[o] = gamma[o] * rstd * scale;
            g_cs[o]    = beta[o] - gamma[o] * mean[o] * rstd - shift[o];
        }
        return;
    }
    // ---- signcast: tile = 128 channels x 32 hw ----
    __shared__ uint8_t tile[128][33];
    int s2 = blk - 64;
    int hwb = s2 % 25;
    int r2  = s2 / 25;
    int c0  = (r2 & 3) * 128;
    int b   = r2 >> 2;
    int h0  = hwb * 32;
    int tx = tid & 31, ty = tid >> 5;
#pragma unroll
    for (int j = 0; j < 16; j++) {
        int cl = ty + j * 8;
        int c  = c0 + cl;
        int hw = h0 + tx;
        float v = 1.f;
        if (hw < HW_) v = x[((size_t)b * C_ + c) * HW_ + hw] + rb[c];
        tile[cl][tx] = v >= 0.f ? FP8_P1 : FP8_M1;
    }
    __syncthreads();
#pragma unroll
    for (int j = 0; j < 4; j++) {
        int hwl = ty + j * 8;
        int hw  = h0 + hwl;
        if (hw < HW_) {
            size_t m = (size_t)b * HW_ + hw;
            uchar4 u;
            u.x = tile[4 * tx + 0][hwl];
            u.y = tile[4 * tx + 1][hwl];
            u.z = tile[4 * tx + 2][hwl];
            u.w = tile[4 * tx + 3][hwl];
            *(uchar4*)(g_A + m * C_ + c0 + 4 * tx) = u;
        }
    }
}

// ===================== kernel 2: fp8 GEMM + fused epilogue (occ 2) =================
DEV_INLINE void load_a_chunk(uint32_t sb, int q, int mt0, int tid) {
    const int mt = mt0 + (q >> 2), kc = q & 3;
    const uint8_t* src = g_A + (size_t)mt * BM * C_ + kc * BKB;
    uint32_t dst = sb + OFF_A + (q & 1) * 16384;
#pragma unroll
    for (int i = tid; i < 1024; i += 256) {
        int row = i >> 3, g = i & 7;
        cp_async16(dst + sw_off(row, g), src + (size_t)row * C_ + g * 16);
    }
}

__global__ __launch_bounds__(256, 2)
void lb_gemm_kernel(const float* __restrict__ x, float* __restrict__ out,
                    const float* __restrict__ pr_slope, const float* __restrict__ pr_bias) {
    extern __shared__ char smem[];
    const uint32_t sb = smem_u32(smem);
    const int tid = threadIdx.x, lane = tid & 31, w = tid >> 5;
    const int n0  = blockIdx.x * BN;
    const int mt0 = blockIdx.y * MT;

    // ---- B tile (resident, 4 chunks) + A chunk 0 : one cp.async group ----
    for (int i = tid; i < 4096; i += 256) {
        int kc = i >> 10, row = (i >> 3) & 127, g = i & 7;
        cp_async16(sb + OFF_B + kc * 16384 + sw_off(row, g),
                   g_W + (size_t)(n0 + row) * C_ + kc * BKB + g * 16);
    }
    load_a_chunk(sb, 0, mt0, tid);
    cp_commit();

    const int m_off = (w & 1) * 64, n_off = (w >> 1) * 32;
    const int ra      = lane & 15;
    const int ka_half = lane >> 4;
    const int rb_     = (lane & 7) + ((lane >> 4) << 3);
    const int kb_half = (lane >> 3) & 1;

    float acc[4][4][4];
#pragma unroll
    for (int mf = 0; mf < 4; mf++)
#pragma unroll
        for (int nf = 0; nf < 4; nf++)
#pragma unroll
            for (int e = 0; e < 4; e++) acc[mf][nf][e] = 0.f;

#pragma unroll 1
    for (int q = 0; q < QTOT; q++) {
        cp_wait<0>();
        __syncthreads();
        if (q + 1 < QTOT) load_a_chunk(sb, q + 1, mt0, tid);
        cp_commit();   // empty group at tail is harmless

        const uint32_t Ab = sb + OFF_A + (q & 1) * 16384;
        const uint32_t Bb = sb + OFF_B + (q & 3) * 16384;
#pragma unroll
        for (int ks = 0; ks < 4; ks++) {
            uint32_t afr[4][4];
#pragma unroll
            for (int mf = 0; mf < 4; mf++) {
                int row = m_off + mf * 16 + ra;
                ldmatrix_x4(afr[mf], Ab + sw_off(row, ks * 2 + ka_half));
            }
            uint32_t bfr[2][4];
#pragma unroll
            for (int p = 0; p < 2; p++) {
                int row = n_off + p * 16 + rb_;
                ldmatrix_x4(bfr[p], Bb + sw_off(row, ks * 2 + kb_half));
            }
#pragma unroll
            for (int mf = 0; mf < 4; mf++)
#pragma unroll
                for (int nf = 0; nf < 4; nf++)
                    mma_fp8(acc[mf][nf], afr[mf], &bfr[nf >> 1][(nf & 1) * 2]);
        }

        if ((q & 3) == 3) {
            // ---- epilogue for m-tile (q>>2); A(q+1) prefetch already in flight ----
            const int mbase = (mt0 + (q >> 2)) * BM;
            float* epi = (float*)(smem + OFF_EPI);   // [128][33]
#pragma unroll 1
            for (int nc = 0; nc < 4; nc++) {
                if ((w >> 1) == nc) {
#pragma unroll
                    for (int mf = 0; mf < 4; mf++)
#pragma unroll
                        for (int nf = 0; nf < 4; nf++) {
                            int r = m_off + mf * 16 + (lane >> 2);
                            int c = nf * 8 + (lane & 3) * 2;
                            epi[r * 33 + c]           = acc[mf][nf][0];
                            epi[r * 33 + c + 1]       = acc[mf][nf][1];
                            epi[(r + 8) * 33 + c]     = acc[mf][nf][2];
                            epi[(r + 8) * 33 + c + 1] = acc[mf][nf][3];
                        }
                }
                __syncthreads();
                {
                    const int nl = tid >> 3, ms = tid & 7;
                    const int n = n0 + nc * 32 + nl;
                    const float al  = g_alpha[n];
                    const float c0v = g_cs[n];
                    const float sl  = pr_slope[n];
                    const float pb  = pr_bias[n];
                    const int m = mbase + ms * 16;          // 784 % 16 == 0
                    const int bb = m / HW_, hw = m % HW_;
                    const size_t base = ((size_t)bb * C_ + n) * HW_ + hw;
#pragma unroll
                    for (int j = 0; j < 4; j++) {
                        float4 xv = *(const float4*)(x + base + j * 4);
                        float d0 = epi[(ms * 16 + j * 4 + 0) * 33 + nl];
                        float d1 = epi[(ms * 16 + j * 4 + 1) * 33 + nl];
                        float d2 = epi[(ms * 16 + j * 4 + 2) * 33 + nl];
                        float d3 = epi[(ms * 16 + j * 4 + 3) * 33 + nl];
                        float t0 = al * d0 + c0v + xv.x;
                        float t1 = al * d1 + c0v + xv.y;
                        float t2 = al * d2 + c0v + xv.z;
                        float t3 = al * d3 + c0v + xv.w;
                        float4 o;
                        o.x = (t0 > 0.f ? t0 : sl * t0) + pb;
                        o.y = (t1 > 0.f ? t1 : sl * t1) + pb;
                        o.z = (t2 > 0.f ? t2 : sl * t2) + pb;
                        o.w = (t3 > 0.f ? t3 : sl * t3) + pb;
                        *(float4*)(out + base + j * 4) = o;
                    }
                }
                __syncthreads();
            }
            if (q + 1 < QTOT) {
#pragma unroll
                for (int mf = 0; mf < 4; mf++)
#pragma unroll
                    for (int nf = 0; nf < 4; nf++)
#pragma unroll
                        for (int e = 0; e < 4; e++) acc[mf][nf][e] = 0.f;
            }
        }
    }
}

// ===================== launch =====================
extern "C" void kernel_launch(void* const* d_in, const int* in_sizes, int n_in,
                              void* d_out, int out_size) {
    const float* x     = (const float*)d_in[0];
    const float* rb    = (const float*)d_in[1];
    const float* W     = (const float*)d_in[2];
    const float* gamma = (const float*)d_in[3];
    const float* beta  = (const float*)d_in[4];
    const float* mean  = (const float*)d_in[5];
    const float* var   = (const float*)d_in[6];
    const float* slope = (const float*)d_in[7];
    const float* shift = (const float*)d_in[8];
    const float* prb   = (const float*)d_in[9];
    float* out = (float*)d_out;

    lb_prepsign_kernel<<<64 + 25 * 4 * B_, 256>>>(x, rb, W, gamma, beta, mean, var, shift);

    cudaFuncSetAttribute(lb_gemm_kernel, cudaFuncAttributeMaxDynamicSharedMemorySize, SMEM_BYTES);
    lb_gemm_kernel<<<dim3(C_ / BN, MTILES / MT), 256, SMEM_BYTES>>>(x, out, slope, prb);
}